// round 14
// baseline (speedup 1.0000x reference)
#include <cuda_runtime.h>
#include <cuda_fp16.h>
#include <cstdint>
#include <cstddef>

#define BB 64
#define LL 4096
#define HH 128
#define NLAYER 4
#define EPSF 1e-5f

// ---- smem layout (bytes), M=128 tile ----
#define SH_HI   0
#define SH_LO   33280
#define TMP_HI  66560
#define TMP_LO  99328
#define BST     132096         // 4 stages x 8KB (4KB hi + 4KB lo)
#define BIAS    164864
#define SMEM_TOTAL 166912
// xbuf fp32 (128 x 136 = 69632B) aliases TMP_HI..(+4KB into BST), used only after GEMM2

static __device__ __align__(16) float g_buf0[(size_t)BB * LL * HH];
static __device__ __align__(16) float g_buf1[(size_t)BB * LL * HH];
static __device__ __align__(16) float g_buf2[(size_t)BB * LL * HH];
static __device__ __align__(16) __half g_W1hi[NLAYER * 3 * HH * HH];
static __device__ __align__(16) __half g_W1lo[NLAYER * 3 * HH * HH];
static __device__ __align__(16) __half g_W2hi[NLAYER * HH * HH];
static __device__ __align__(16) __half g_W2lo[NLAYER * HH * HH];
static __device__ float g_scores[BB * LL];
static __device__ float g_part[BB * 8 * HH];

__device__ __forceinline__ float* bsel(int i) {
    return i == 0 ? g_buf0 : i == 1 ? g_buf1 : g_buf2;
}

__device__ __forceinline__ uint32_t swz(int r, int c) {
    return (uint32_t)((r << 8) + (((c >> 3) ^ (r & 7)) << 4) + ((c & 7) << 1));
}
__device__ __forceinline__ void ldsm4(uint32_t a, uint32_t* r) {
    asm volatile("ldmatrix.sync.aligned.m8n8.x4.shared.b16 {%0,%1,%2,%3}, [%4];\n"
                 : "=r"(r[0]), "=r"(r[1]), "=r"(r[2]), "=r"(r[3]) : "r"(a));
}
__device__ __forceinline__ void ldsm4t(uint32_t a, uint32_t* r) {
    asm volatile("ldmatrix.sync.aligned.m8n8.x4.trans.shared.b16 {%0,%1,%2,%3}, [%4];\n"
                 : "=r"(r[0]), "=r"(r[1]), "=r"(r[2]), "=r"(r[3]) : "r"(a));
}
__device__ __forceinline__ void mma_16816(float* d, const uint32_t* a, const uint32_t* b) {
    asm volatile(
        "mma.sync.aligned.m16n8k16.row.col.f32.f16.f16.f32 "
        "{%0,%1,%2,%3}, {%4,%5,%6,%7}, {%8,%9}, {%0,%1,%2,%3};\n"
        : "+f"(d[0]), "+f"(d[1]), "+f"(d[2]), "+f"(d[3])
        : "r"(a[0]), "r"(a[1]), "r"(a[2]), "r"(a[3]), "r"(b[0]), "r"(b[1]));
}

// stage one 16x128 k-tile of hi/lo weights into 4-stage smem ring (block-wide)
__device__ __forceinline__ void bload(const __half* Bhi, const __half* Blo,
                                      int c, int stage, int tid, uint32_t sb) {
    int r = tid >> 4, q = tid & 15;
    uint32_t dst = sb + BST + (uint32_t)stage * 8192u
                 + (uint32_t)(r * 256 + ((q ^ (r & 7)) << 4));
    const __half* s1 = Bhi + (c * 16 + r) * 128 + q * 8;
    const __half* s2 = Blo + (c * 16 + r) * 128 + q * 8;
    asm volatile("cp.async.ca.shared.global [%0], [%1], 16;\n" :: "r"(dst), "l"(s1));
    asm volatile("cp.async.ca.shared.global [%0], [%1], 16;\n" :: "r"(dst + 4096u), "l"(s2));
}
#define CPCOMMIT() asm volatile("cp.async.commit_group;\n")

__global__ void k_prep(const float* __restrict__ W1, const float* __restrict__ W2) {
    int i = blockIdx.x * blockDim.x + threadIdx.x;
    if (i < NLAYER * 3 * HH * HH) {
        float v = W1[i];
        __half h = __float2half_rn(v);
        g_W1hi[i] = h;
        g_W1lo[i] = __float2half_rn(v - __half2float(h));
    }
    if (i < NLAYER * HH * HH) {
        float v = W2[i];
        __half h = __float2half_rn(v);
        g_W2hi[i] = h;
        g_W2lo[i] = __float2half_rn(v - __half2float(h));
    }
}

__global__ void k_proj(const float* __restrict__ tokens, const float* __restrict__ Wp,
                       const float* __restrict__ bp) {
    int g = blockIdx.x * blockDim.x + threadIdx.x;
    int tok = g >> 5;
    int c = (g & 31) * 4;
    const float* tr = tokens + (size_t)tok * 8;
    float tv[8];
#pragma unroll
    for (int i = 0; i < 8; ++i) tv[i] = tr[i];
    float4 acc;
    acc.x = bp[c]; acc.y = bp[c + 1]; acc.z = bp[c + 2]; acc.w = bp[c + 3];
#pragma unroll
    for (int i = 0; i < 8; ++i) {
        float4 w = *(const float4*)(Wp + i * HH + c);
        acc.x += tv[i] * w.x; acc.y += tv[i] * w.y;
        acc.z += tv[i] * w.z; acc.w += tv[i] * w.w;
    }
    *(float4*)(g_buf0 + (size_t)tok * HH + c) = acc;
}

__global__ void __launch_bounds__(256, 1)
k_layer(int layer, int dirn, int insel, int outsel,
        const float* __restrict__ b1g, const float* __restrict__ b2g,
        const float* __restrict__ gammag, const float* __restrict__ betag) {
    extern __shared__ char smc[];
    const uint32_t sb = (uint32_t)__cvta_generic_to_shared(smc);
    const int tid = threadIdx.x;
    const int lane = tid & 31, warp = tid >> 5;
    const int wm = warp & 1, wn = warp >> 1;   // 2m x 4n; warp tile m64 x n32
    const int lr = lane & 15;
    const int lc = (lane >> 4) << 3;
    const int b = blockIdx.y;
    const int t0 = blockIdx.x * 128;

    float* b1s = (float*)(smc + BIAS);
    float* b2s = b1s + 128;
    float* gs  = b1s + 256;
    float* bes = b1s + 384;
    if (tid < 128) {
        b1s[tid] = b1g[layer * HH + tid];
        b2s[tid] = b2g[layer * HH + tid];
        gs[tid]  = gammag[layer * HH + tid];
        bes[tid] = betag[layer * HH + tid];
    }

    // load h rows [t0-1, t0+128] (circular) as split fp16, 8B vector stores
    const float* hin = bsel(insel);
    for (int f = tid; f < 130 * 32; f += 256) {
        int r = f >> 5, c4 = f & 31;
        int gl = (t0 - 1 + r + LL) & (LL - 1);
        float4 v = *(const float4*)(hin + ((size_t)b * LL + gl) * HH + c4 * 4);
        __half2 h01 = __floats2half2_rn(v.x, v.y);
        __half2 h23 = __floats2half2_rn(v.z, v.w);
        __half2 l01 = __floats2half2_rn(v.x - __low2float(h01), v.y - __high2float(h01));
        __half2 l23 = __floats2half2_rn(v.z - __low2float(h23), v.w - __high2float(h23));
        uint32_t o = swz(r, c4 * 4);
        uint2 hv, lv;
        hv.x = *(uint32_t*)&h01; hv.y = *(uint32_t*)&h23;
        lv.x = *(uint32_t*)&l01; lv.y = *(uint32_t*)&l23;
        *(uint2*)(smc + SH_HI + o) = hv;
        *(uint2*)(smc + SH_LO + o) = lv;
    }
    __syncthreads();

    float acc[4][4][4];
#pragma unroll
    for (int mt = 0; mt < 4; ++mt)
#pragma unroll
        for (int nt = 0; nt < 4; ++nt)
#pragma unroll
            for (int e = 0; e < 4; ++e) acc[mt][nt][e] = 0.f;

    const __half* W1hi = g_W1hi + (size_t)layer * 3 * HH * HH;
    const __half* W1lo = g_W1lo + (size_t)layer * 3 * HH * HH;
    const __half* W2hi = g_W2hi + (size_t)layer * HH * HH;
    const __half* W2lo = g_W2lo + (size_t)layer * HH * HH;

    // ---- GEMM1: K=384, 24 k-tiles, 4-stage ring depth 3 ----
    bload(W1hi, W1lo, 0, 0, tid, sb); CPCOMMIT();
    bload(W1hi, W1lo, 1, 1, tid, sb); CPCOMMIT();
    bload(W1hi, W1lo, 2, 2, tid, sb); CPCOMMIT();
#pragma unroll
    for (int c = 0; c < 24; ++c) {
        if (c <= 21)      asm volatile("cp.async.wait_group 2;\n");
        else if (c == 22) asm volatile("cp.async.wait_group 1;\n");
        else              asm volatile("cp.async.wait_group 0;\n");
        __syncthreads();
        if (c + 3 < 24) {
            bload(W1hi, W1lo, c + 3, (c + 3) & 3, tid, sb); CPCOMMIT();
        }
        int off = ((c >> 3) - 1) * dirn;
        int arb = wm * 64 + 1 + off + lr;
        int acol = (c & 7) * 16 + lc;
        uint32_t ahi[4][4], alo[4][4], bhi[2][4], blo[2][4];
#pragma unroll
        for (int mt = 0; mt < 4; ++mt) {
            ldsm4(sb + SH_HI + swz(arb + mt * 16, acol), ahi[mt]);
            ldsm4(sb + SH_LO + swz(arb + mt * 16, acol), alo[mt]);
        }
        uint32_t bbs = sb + BST + (uint32_t)(c & 3) * 8192u;
#pragma unroll
        for (int g = 0; g < 2; ++g) {
            uint32_t ba = bbs + swz(lr, wn * 32 + g * 16 + lc);
            ldsm4t(ba, bhi[g]);
            ldsm4t(ba + 4096u, blo[g]);
        }
#pragma unroll
        for (int mt = 0; mt < 4; ++mt)
#pragma unroll
            for (int g = 0; g < 2; ++g)
#pragma unroll
                for (int j = 0; j < 2; ++j) {
                    mma_16816(acc[mt][g * 2 + j], ahi[mt], &bhi[g][j * 2]);
                    mma_16816(acc[mt][g * 2 + j], ahi[mt], &blo[g][j * 2]);
                    mma_16816(acc[mt][g * 2 + j], alo[mt], &bhi[g][j * 2]);
                }
    }

    // bias + relu -> split fp16 -> TMP
#pragma unroll
    for (int mt = 0; mt < 4; ++mt)
#pragma unroll
        for (int nt = 0; nt < 4; ++nt) {
            int r0 = wm * 64 + mt * 16 + (lane >> 2);
            int c0 = wn * 32 + nt * 8 + ((lane & 3) << 1);
            float v0 = fmaxf(acc[mt][nt][0] + b1s[c0],     0.f);
            float v1 = fmaxf(acc[mt][nt][1] + b1s[c0 + 1], 0.f);
            float v2 = fmaxf(acc[mt][nt][2] + b1s[c0],     0.f);
            float v3 = fmaxf(acc[mt][nt][3] + b1s[c0 + 1], 0.f);
            __half2 hA = __floats2half2_rn(v0, v1);
            __half2 hB = __floats2half2_rn(v2, v3);
            __half2 lA = __floats2half2_rn(v0 - __low2float(hA), v1 - __high2float(hA));
            __half2 lB = __floats2half2_rn(v2 - __low2float(hB), v3 - __high2float(hB));
            *(__half2*)(smc + TMP_HI + swz(r0, c0))     = hA;
            *(__half2*)(smc + TMP_LO + swz(r0, c0))     = lA;
            *(__half2*)(smc + TMP_HI + swz(r0 + 8, c0)) = hB;
            *(__half2*)(smc + TMP_LO + swz(r0 + 8, c0)) = lB;
            acc[mt][nt][0] = acc[mt][nt][1] = acc[mt][nt][2] = acc[mt][nt][3] = 0.f;
        }

    // ---- GEMM2: K=128, 8 k-tiles; preload W2 stages 0-2 (slots free: last reads
    //      were G1 iters 20/21/22, all before the c=23 barrier every warp passed) ----
    bload(W2hi, W2lo, 0, 0, tid, sb); CPCOMMIT();
    bload(W2hi, W2lo, 1, 1, tid, sb); CPCOMMIT();
    bload(W2hi, W2lo, 2, 2, tid, sb); CPCOMMIT();
#pragma unroll
    for (int c = 0; c < 8; ++c) {
        if (c <= 5)      asm volatile("cp.async.wait_group 2;\n");
        else if (c == 6) asm volatile("cp.async.wait_group 1;\n");
        else             asm volatile("cp.async.wait_group 0;\n");
        __syncthreads();   // c==0: also makes TMP stores visible
        if (c + 3 < 8) {
            bload(W2hi, W2lo, c + 3, (c + 3) & 3, tid, sb); CPCOMMIT();
        }
        int acol = c * 16 + lc;
        uint32_t ahi[4][4], alo[4][4], bhi[2][4], blo[2][4];
#pragma unroll
        for (int mt = 0; mt < 4; ++mt) {
            int ar = wm * 64 + mt * 16 + lr;
            ldsm4(sb + TMP_HI + swz(ar, acol), ahi[mt]);
            ldsm4(sb + TMP_LO + swz(ar, acol), alo[mt]);
        }
        uint32_t bbs = sb + BST + (uint32_t)(c & 3) * 8192u;
#pragma unroll
        for (int g = 0; g < 2; ++g) {
            uint32_t ba = bbs + swz(lr, wn * 32 + g * 16 + lc);
            ldsm4t(ba, bhi[g]);
            ldsm4t(ba + 4096u, blo[g]);
        }
#pragma unroll
        for (int mt = 0; mt < 4; ++mt)
#pragma unroll
            for (int g = 0; g < 2; ++g)
#pragma unroll
                for (int j = 0; j < 2; ++j) {
                    mma_16816(acc[mt][g * 2 + j], ahi[mt], &bhi[g][j * 2]);
                    mma_16816(acc[mt][g * 2 + j], ahi[mt], &blo[g][j * 2]);
                    mma_16816(acc[mt][g * 2 + j], alo[mt], &bhi[g][j * 2]);
                }
    }
    __syncthreads();   // all TMP reads done before xbuf aliases it

    // stash delta fp32 in xbuf (aliases TMP + first 4KB of BST slot 0)
    float* xbuf = (float*)(smc + TMP_HI);
#pragma unroll
    for (int mt = 0; mt < 4; ++mt)
#pragma unroll
        for (int nt = 0; nt < 4; ++nt) {
            int r0 = wm * 64 + mt * 16 + (lane >> 2);
            int c0 = wn * 32 + nt * 8 + ((lane & 3) << 1);
            xbuf[r0 * 136 + c0]           = acc[mt][nt][0];
            xbuf[r0 * 136 + c0 + 1]       = acc[mt][nt][1];
            xbuf[(r0 + 8) * 136 + c0]     = acc[mt][nt][2];
            xbuf[(r0 + 8) * 136 + c0 + 1] = acc[mt][nt][3];
        }
    __syncthreads();

    // LN + relu epilogue: 2 threads per row (128 rows), 8B vector smem reads
    {
        int row = tid >> 1;
        int cb = (tid & 1) * 64;
        float s = 0.f, s2 = 0.f;
#pragma unroll
        for (int c16 = 0; c16 < 16; ++c16) {
            int c = cb + c16 * 4;
            uint32_t o = swz(row + 1, c);
            uint2 H2 = *(uint2*)(smc + SH_HI + o);
            uint2 L2 = *(uint2*)(smc + SH_LO + o);
            __half2 hh0 = *(__half2*)&H2.x, hh1 = *(__half2*)&H2.y;
            __half2 ll0 = *(__half2*)&L2.x, ll1 = *(__half2*)&L2.y;
            float x0 = __low2float(hh0)  + __low2float(ll0)  + xbuf[row * 136 + c]     + b2s[c];
            float x1 = __high2float(hh0) + __high2float(ll0) + xbuf[row * 136 + c + 1] + b2s[c + 1];
            float x2 = __low2float(hh1)  + __low2float(ll1)  + xbuf[row * 136 + c + 2] + b2s[c + 2];
            float x3 = __high2float(hh1) + __high2float(ll1) + xbuf[row * 136 + c + 3] + b2s[c + 3];
            s += x0 + x1 + x2 + x3;
            s2 += x0 * x0 + x1 * x1 + x2 * x2 + x3 * x3;
        }
        s  += __shfl_xor_sync(0xffffffffu, s, 1);
        s2 += __shfl_xor_sync(0xffffffffu, s2, 1);
        float mu = s * (1.f / 128.f);
        float var = fmaxf(s2 * (1.f / 128.f) - mu * mu, 0.f);
        float rs = rsqrtf(var + EPSF);
        float* outp = bsel(outsel) + ((size_t)b * LL + t0 + row) * HH;
#pragma unroll
        for (int c16 = 0; c16 < 16; ++c16) {
            int c = cb + c16 * 4;
            uint32_t o = swz(row + 1, c);
            uint2 H2 = *(uint2*)(smc + SH_HI + o);
            uint2 L2 = *(uint2*)(smc + SH_LO + o);
            __half2 hh0 = *(__half2*)&H2.x, hh1 = *(__half2*)&H2.y;
            __half2 ll0 = *(__half2*)&L2.x, ll1 = *(__half2*)&L2.y;
            float x0 = __low2float(hh0)  + __low2float(ll0)  + xbuf[row * 136 + c]     + b2s[c];
            float x1 = __high2float(hh0) + __high2float(ll0) + xbuf[row * 136 + c + 1] + b2s[c + 1];
            float x2 = __low2float(hh1)  + __low2float(ll1)  + xbuf[row * 136 + c + 2] + b2s[c + 2];
            float x3 = __high2float(hh1) + __high2float(ll1) + xbuf[row * 136 + c + 3] + b2s[c + 3];
            float4 ov;
            ov.x = fmaxf((x0 - mu) * rs * gs[c]     + bes[c],     0.f);
            ov.y = fmaxf((x1 - mu) * rs * gs[c + 1] + bes[c + 1], 0.f);
            ov.z = fmaxf((x2 - mu) * rs * gs[c + 2] + bes[c + 2], 0.f);
            ov.w = fmaxf((x3 - mu) * rs * gs[c + 3] + bes[c + 3], 0.f);
            *(float4*)(outp + c) = ov;
        }
    }
}

// h = 0.5*(fwd + rev) -> out; scores = h @ Ws + bs
__global__ void k_combine(float* __restrict__ out, const float* __restrict__ Ws,
                          const float* __restrict__ bs) {
    int row = blockIdx.x * 8 + (threadIdx.x >> 5);
    int lane = threadIdx.x & 31;
    int c = lane * 4;
    size_t base = (size_t)row * HH + c;
    float4 a = *(const float4*)(g_buf2 + base);
    float4 bq = *(const float4*)(g_buf0 + base);
    float4 h;
    h.x = 0.5f * (a.x + bq.x); h.y = 0.5f * (a.y + bq.y);
    h.z = 0.5f * (a.z + bq.z); h.w = 0.5f * (a.w + bq.w);
    *(float4*)(out + base) = h;
    float4 w = *(const float4*)(Ws + c);
    float s = h.x * w.x + h.y * w.y + h.z * w.z + h.w * w.w;
#pragma unroll
    for (int m = 16; m; m >>= 1) s += __shfl_xor_sync(0xffffffffu, s, m);
    if (lane == 0) g_scores[row] = s + bs[0];
}

__global__ void k_softmax() {
    __shared__ float red[256];
    int b = blockIdx.x, tid = threadIdx.x;
    float* sc = g_scores + (size_t)b * LL;
    float m = -1e30f;
    for (int k = 0; k < 16; ++k) m = fmaxf(m, sc[tid + k * 256]);
    red[tid] = m; __syncthreads();
    for (int st = 128; st; st >>= 1) {
        if (tid < st) red[tid] = fmaxf(red[tid], red[tid + st]);
        __syncthreads();
    }
    m = red[0]; __syncthreads();
    float s = 0.f;
    for (int k = 0; k < 16; ++k) s += __expf(sc[tid + k * 256] - m);
    red[tid] = s; __syncthreads();
    for (int st = 128; st; st >>= 1) {
        if (tid < st) red[tid] += red[tid + st];
        __syncthreads();
    }
    float inv = 1.f / red[0];
    for (int k = 0; k < 16; ++k) {
        int i = tid + k * 256;
        sc[i] = __expf(sc[i] - m) * inv;
    }
}

__global__ void k_pool(const float* __restrict__ h) {
    int j = blockIdx.x, b = blockIdx.y, c = threadIdx.x;
    const float* w = g_scores + (size_t)b * LL + j * 512;
    const float* hp = h + ((size_t)b * LL + j * 512) * HH + c;
    float acc = 0.f;
#pragma unroll 4
    for (int l = 0; l < 512; ++l) acc += w[l] * hp[(size_t)l * HH];
    g_part[(b * 8 + j) * HH + c] = acc;
}

__global__ void k_reduce(float* __restrict__ outp) {
    int b = blockIdx.x, c = threadIdx.x;
    float s = 0.f;
#pragma unroll
    for (int j = 0; j < 8; ++j) s += g_part[(b * 8 + j) * HH + c];
    outp[(size_t)b * HH + c] = s;
}

extern "C" void kernel_launch(void* const* d_in, const int* in_sizes, int n_in,
                              void* d_out, int out_size) {
    const float* tokens = (const float*)d_in[0];
    const float* Wp     = (const float*)d_in[1];
    const float* bp     = (const float*)d_in[2];
    const float* W1     = (const float*)d_in[3];
    const float* b1     = (const float*)d_in[4];
    const float* W2     = (const float*)d_in[5];
    const float* b2     = (const float*)d_in[6];
    const float* gamma  = (const float*)d_in[7];
    const float* beta   = (const float*)d_in[8];
    const float* Ws     = (const float*)d_in[9];
    const float* bs     = (const float*)d_in[10];
    float* out = (float*)d_out;

    cudaFuncSetAttribute(k_layer, cudaFuncAttributeMaxDynamicSharedMemorySize, SMEM_TOTAL);

    k_prep<<<768, 256>>>(W1, W2);
    k_proj<<<32768, 256>>>(tokens, Wp, bp);

    dim3 lgrid(32, 64);
    // forward: buf0 -> 1 -> 2 -> 1 -> 2
    k_layer<<<lgrid, 256, SMEM_TOTAL>>>(0, 1, 0, 1, b1, b2, gamma, beta);
    k_layer<<<lgrid, 256, SMEM_TOTAL>>>(1, 1, 1, 2, b1, b2, gamma, beta);
    k_layer<<<lgrid, 256, SMEM_TOTAL>>>(2, 1, 2, 1, b1, b2, gamma, beta);
    k_layer<<<lgrid, 256, SMEM_TOTAL>>>(3, 1, 1, 2, b1, b2, gamma, beta);
    // reverse: buf0 -> 1 -> 0 -> 1 -> 0
    k_layer<<<lgrid, 256, SMEM_TOTAL>>>(0, -1, 0, 1, b1, b2, gamma, beta);
    k_layer<<<lgrid, 256, SMEM_TOTAL>>>(1, -1, 1, 0, b1, b2, gamma, beta);
    k_layer<<<lgrid, 256, SMEM_TOTAL>>>(2, -1, 0, 1, b1, b2, gamma, beta);
    k_layer<<<lgrid, 256, SMEM_TOTAL>>>(3, -1, 1, 0, b1, b2, gamma, beta);

    k_combine<<<32768, 256>>>(out, Ws, bs);
    k_softmax<<<64, 256>>>();
    k_pool<<<dim3(8, 64), 128>>>(out);
    k_reduce<<<64, 128>>>(out + (size_t)BB * LL * HH);
}

// round 15
// speedup vs baseline: 1.0175x; 1.0175x over previous
#include <cuda_runtime.h>
#include <cuda_fp16.h>
#include <cstdint>
#include <cstddef>

#define BB 64
#define LL 4096
#define HH 128
#define NLAYER 4
#define EPSF 1e-5f

// ---- smem layout (bytes), M=128 tile ----
#define SH_HI   0
#define SH_LO   33280
#define TMP_HI  66560
#define TMP_LO  99328
#define BST     132096         // 4 stages x 8KB (4KB hi + 4KB lo)
#define BIAS    164864
#define SMEM_TOTAL 166912
// xbuf fp32 (128 x 136 = 69632B) aliases TMP_HI..(+4KB into BST), used only after GEMM2

static __device__ __align__(16) float g_buf0[(size_t)BB * LL * HH];
static __device__ __align__(16) float g_buf1[(size_t)BB * LL * HH];
static __device__ __align__(16) float g_buf2[(size_t)BB * LL * HH];
static __device__ __align__(16) __half g_W1hi[NLAYER * 3 * HH * HH];
static __device__ __align__(16) __half g_W1lo[NLAYER * 3 * HH * HH];
static __device__ __align__(16) __half g_W2hi[NLAYER * HH * HH];
static __device__ __align__(16) __half g_W2lo[NLAYER * HH * HH];
static __device__ float g_scores[BB * LL];
static __device__ float g_part[BB * 8 * HH];

__device__ __forceinline__ float* bsel(int i) {
    return i == 0 ? g_buf0 : i == 1 ? g_buf1 : g_buf2;
}

__device__ __forceinline__ uint32_t swz(int r, int c) {
    return (uint32_t)((r << 8) + (((c >> 3) ^ (r & 7)) << 4) + ((c & 7) << 1));
}
__device__ __forceinline__ void ldsm4(uint32_t a, uint32_t* r) {
    asm volatile("ldmatrix.sync.aligned.m8n8.x4.shared.b16 {%0,%1,%2,%3}, [%4];\n"
                 : "=r"(r[0]), "=r"(r[1]), "=r"(r[2]), "=r"(r[3]) : "r"(a));
}
__device__ __forceinline__ void ldsm4t(uint32_t a, uint32_t* r) {
    asm volatile("ldmatrix.sync.aligned.m8n8.x4.trans.shared.b16 {%0,%1,%2,%3}, [%4];\n"
                 : "=r"(r[0]), "=r"(r[1]), "=r"(r[2]), "=r"(r[3]) : "r"(a));
}
__device__ __forceinline__ void mma_16816(float* d, const uint32_t* a, const uint32_t* b) {
    asm volatile(
        "mma.sync.aligned.m16n8k16.row.col.f32.f16.f16.f32 "
        "{%0,%1,%2,%3}, {%4,%5,%6,%7}, {%8,%9}, {%0,%1,%2,%3};\n"
        : "+f"(d[0]), "+f"(d[1]), "+f"(d[2]), "+f"(d[3])
        : "r"(a[0]), "r"(a[1]), "r"(a[2]), "r"(a[3]), "r"(b[0]), "r"(b[1]));
}

// stage one 16x128 k-tile of hi/lo weights into 4-stage smem ring (block-wide)
__device__ __forceinline__ void bload(const __half* Bhi, const __half* Blo,
                                      int c, int stage, int tid, uint32_t sb) {
    int r = tid >> 4, q = tid & 15;
    uint32_t dst = sb + BST + (uint32_t)stage * 8192u
                 + (uint32_t)(r * 256 + ((q ^ (r & 7)) << 4));
    const __half* s1 = Bhi + (c * 16 + r) * 128 + q * 8;
    const __half* s2 = Blo + (c * 16 + r) * 128 + q * 8;
    asm volatile("cp.async.ca.shared.global [%0], [%1], 16;\n" :: "r"(dst), "l"(s1));
    asm volatile("cp.async.ca.shared.global [%0], [%1], 16;\n" :: "r"(dst + 4096u), "l"(s2));
}
#define CPCOMMIT() asm volatile("cp.async.commit_group;\n")

__global__ void k_prep(const float* __restrict__ W1, const float* __restrict__ W2) {
    int i = blockIdx.x * blockDim.x + threadIdx.x;
    if (i < NLAYER * 3 * HH * HH) {
        float v = W1[i];
        __half h = __float2half_rn(v);
        g_W1hi[i] = h;
        g_W1lo[i] = __float2half_rn(v - __half2float(h));
    }
    if (i < NLAYER * HH * HH) {
        float v = W2[i];
        __half h = __float2half_rn(v);
        g_W2hi[i] = h;
        g_W2lo[i] = __float2half_rn(v - __half2float(h));
    }
}

__global__ void k_proj(const float* __restrict__ tokens, const float* __restrict__ Wp,
                       const float* __restrict__ bp) {
    int g = blockIdx.x * blockDim.x + threadIdx.x;
    int tok = g >> 5;
    int c = (g & 31) * 4;
    const float* tr = tokens + (size_t)tok * 8;
    float tv[8];
#pragma unroll
    for (int i = 0; i < 8; ++i) tv[i] = tr[i];
    float4 acc;
    acc.x = bp[c]; acc.y = bp[c + 1]; acc.z = bp[c + 2]; acc.w = bp[c + 3];
#pragma unroll
    for (int i = 0; i < 8; ++i) {
        float4 w = *(const float4*)(Wp + i * HH + c);
        acc.x += tv[i] * w.x; acc.y += tv[i] * w.y;
        acc.z += tv[i] * w.z; acc.w += tv[i] * w.w;
    }
    *(float4*)(g_buf0 + (size_t)tok * HH + c) = acc;
}

__global__ void __launch_bounds__(256, 1)
k_layer(int layer, int dirn, int insel, int outsel,
        const float* __restrict__ b1g, const float* __restrict__ b2g,
        const float* __restrict__ gammag, const float* __restrict__ betag) {
    extern __shared__ char smc[];
    const uint32_t sb = (uint32_t)__cvta_generic_to_shared(smc);
    const int tid = threadIdx.x;
    const int lane = tid & 31, warp = tid >> 5;
    const int wm = warp & 1, wn = warp >> 1;   // 2m x 4n; warp tile m64 x n32
    const int lr = lane & 15;
    const int lc = (lane >> 4) << 3;
    const int b = blockIdx.y;
    const int t0 = blockIdx.x * 128;

    float* b1s = (float*)(smc + BIAS);
    float* b2s = b1s + 128;
    float* gs  = b1s + 256;
    float* bes = b1s + 384;
    if (tid < 128) {
        b1s[tid] = b1g[layer * HH + tid];
        b2s[tid] = b2g[layer * HH + tid];
        gs[tid]  = gammag[layer * HH + tid];
        bes[tid] = betag[layer * HH + tid];
    }

    // load h rows [t0-1, t0+128] (circular) as split fp16, 8B vector stores
    const float* hin = bsel(insel);
    for (int f = tid; f < 130 * 32; f += 256) {
        int r = f >> 5, c4 = f & 31;
        int gl = (t0 - 1 + r + LL) & (LL - 1);
        float4 v = *(const float4*)(hin + ((size_t)b * LL + gl) * HH + c4 * 4);
        __half2 h01 = __floats2half2_rn(v.x, v.y);
        __half2 h23 = __floats2half2_rn(v.z, v.w);
        __half2 l01 = __floats2half2_rn(v.x - __low2float(h01), v.y - __high2float(h01));
        __half2 l23 = __floats2half2_rn(v.z - __low2float(h23), v.w - __high2float(h23));
        uint32_t o = swz(r, c4 * 4);
        uint2 hv, lv;
        hv.x = *(uint32_t*)&h01; hv.y = *(uint32_t*)&h23;
        lv.x = *(uint32_t*)&l01; lv.y = *(uint32_t*)&l23;
        *(uint2*)(smc + SH_HI + o) = hv;
        *(uint2*)(smc + SH_LO + o) = lv;
    }
    __syncthreads();

    float acc[4][4][4];
#pragma unroll
    for (int mt = 0; mt < 4; ++mt)
#pragma unroll
        for (int nt = 0; nt < 4; ++nt)
#pragma unroll
            for (int e = 0; e < 4; ++e) acc[mt][nt][e] = 0.f;

    const __half* W1hi = g_W1hi + (size_t)layer * 3 * HH * HH;
    const __half* W1lo = g_W1lo + (size_t)layer * 3 * HH * HH;
    const __half* W2hi = g_W2hi + (size_t)layer * HH * HH;
    const __half* W2lo = g_W2lo + (size_t)layer * HH * HH;

    // ---- GEMM1: K=384, 24 k-tiles, 4-stage ring depth 3 ----
    bload(W1hi, W1lo, 0, 0, tid, sb); CPCOMMIT();
    bload(W1hi, W1lo, 1, 1, tid, sb); CPCOMMIT();
    bload(W1hi, W1lo, 2, 2, tid, sb); CPCOMMIT();
#pragma unroll
    for (int c = 0; c < 24; ++c) {
        if (c <= 21)      asm volatile("cp.async.wait_group 2;\n");
        else if (c == 22) asm volatile("cp.async.wait_group 1;\n");
        else              asm volatile("cp.async.wait_group 0;\n");
        __syncthreads();
        if (c + 3 < 24) {
            bload(W1hi, W1lo, c + 3, (c + 3) & 3, tid, sb); CPCOMMIT();
        }
        int off = ((c >> 3) - 1) * dirn;
        int arb = wm * 64 + 1 + off + lr;
        int acol = (c & 7) * 16 + lc;
        // B fragments once per k-tile
        uint32_t bhi[2][4], blo[2][4];
        uint32_t bbs = sb + BST + (uint32_t)(c & 3) * 8192u;
#pragma unroll
        for (int g = 0; g < 2; ++g) {
            uint32_t ba = bbs + swz(lr, wn * 32 + g * 16 + lc);
            ldsm4t(ba, bhi[g]);
            ldsm4t(ba + 4096u, blo[g]);
        }
        // software-pipelined A fragments: 2 live sets instead of 4
        uint32_t ahi[2][4], alo[2][4];
        ldsm4(sb + SH_HI + swz(arb, acol), ahi[0]);
        ldsm4(sb + SH_LO + swz(arb, acol), alo[0]);
#pragma unroll
        for (int mt = 0; mt < 4; ++mt) {
            int cur = mt & 1, nxt = cur ^ 1;
            if (mt < 3) {
                ldsm4(sb + SH_HI + swz(arb + (mt + 1) * 16, acol), ahi[nxt]);
                ldsm4(sb + SH_LO + swz(arb + (mt + 1) * 16, acol), alo[nxt]);
            }
#pragma unroll
            for (int g = 0; g < 2; ++g)
#pragma unroll
                for (int j = 0; j < 2; ++j) {
                    mma_16816(acc[mt][g * 2 + j], ahi[cur], &bhi[g][j * 2]);
                    mma_16816(acc[mt][g * 2 + j], ahi[cur], &blo[g][j * 2]);
                    mma_16816(acc[mt][g * 2 + j], alo[cur], &bhi[g][j * 2]);
                }
        }
    }

    // bias + relu -> split fp16 -> TMP
#pragma unroll
    for (int mt = 0; mt < 4; ++mt)
#pragma unroll
        for (int nt = 0; nt < 4; ++nt) {
            int r0 = wm * 64 + mt * 16 + (lane >> 2);
            int c0 = wn * 32 + nt * 8 + ((lane & 3) << 1);
            float v0 = fmaxf(acc[mt][nt][0] + b1s[c0],     0.f);
            float v1 = fmaxf(acc[mt][nt][1] + b1s[c0 + 1], 0.f);
            float v2 = fmaxf(acc[mt][nt][2] + b1s[c0],     0.f);
            float v3 = fmaxf(acc[mt][nt][3] + b1s[c0 + 1], 0.f);
            __half2 hA = __floats2half2_rn(v0, v1);
            __half2 hB = __floats2half2_rn(v2, v3);
            __half2 lA = __floats2half2_rn(v0 - __low2float(hA), v1 - __high2float(hA));
            __half2 lB = __floats2half2_rn(v2 - __low2float(hB), v3 - __high2float(hB));
            *(__half2*)(smc + TMP_HI + swz(r0, c0))     = hA;
            *(__half2*)(smc + TMP_LO + swz(r0, c0))     = lA;
            *(__half2*)(smc + TMP_HI + swz(r0 + 8, c0)) = hB;
            *(__half2*)(smc + TMP_LO + swz(r0 + 8, c0)) = lB;
            acc[mt][nt][0] = acc[mt][nt][1] = acc[mt][nt][2] = acc[mt][nt][3] = 0.f;
        }

    // ---- GEMM2: K=128, 8 k-tiles; preload W2 stages 0-2 (slots free: last reads
    //      were G1 iters 20/21/22, all before the c=23 barrier every warp passed) ----
    bload(W2hi, W2lo, 0, 0, tid, sb); CPCOMMIT();
    bload(W2hi, W2lo, 1, 1, tid, sb); CPCOMMIT();
    bload(W2hi, W2lo, 2, 2, tid, sb); CPCOMMIT();
#pragma unroll
    for (int c = 0; c < 8; ++c) {
        if (c <= 5)      asm volatile("cp.async.wait_group 2;\n");
        else if (c == 6) asm volatile("cp.async.wait_group 1;\n");
        else             asm volatile("cp.async.wait_group 0;\n");
        __syncthreads();   // c==0: also makes TMP stores visible
        if (c + 3 < 8) {
            bload(W2hi, W2lo, c + 3, (c + 3) & 3, tid, sb); CPCOMMIT();
        }
        int acol = c * 16 + lc;
        int arb = wm * 64 + lr;
        uint32_t bhi[2][4], blo[2][4];
        uint32_t bbs = sb + BST + (uint32_t)(c & 3) * 8192u;
#pragma unroll
        for (int g = 0; g < 2; ++g) {
            uint32_t ba = bbs + swz(lr, wn * 32 + g * 16 + lc);
            ldsm4t(ba, bhi[g]);
            ldsm4t(ba + 4096u, blo[g]);
        }
        uint32_t ahi[2][4], alo[2][4];
        ldsm4(sb + TMP_HI + swz(arb, acol), ahi[0]);
        ldsm4(sb + TMP_LO + swz(arb, acol), alo[0]);
#pragma unroll
        for (int mt = 0; mt < 4; ++mt) {
            int cur = mt & 1, nxt = cur ^ 1;
            if (mt < 3) {
                ldsm4(sb + TMP_HI + swz(arb + (mt + 1) * 16, acol), ahi[nxt]);
                ldsm4(sb + TMP_LO + swz(arb + (mt + 1) * 16, acol), alo[nxt]);
            }
#pragma unroll
            for (int g = 0; g < 2; ++g)
#pragma unroll
                for (int j = 0; j < 2; ++j) {
                    mma_16816(acc[mt][g * 2 + j], ahi[cur], &bhi[g][j * 2]);
                    mma_16816(acc[mt][g * 2 + j], ahi[cur], &blo[g][j * 2]);
                    mma_16816(acc[mt][g * 2 + j], alo[cur], &bhi[g][j * 2]);
                }
        }
    }
    __syncthreads();   // all TMP reads done before xbuf aliases it

    // stash delta fp32 in xbuf (aliases TMP + first 4KB of BST slot 0)
    float* xbuf = (float*)(smc + TMP_HI);
#pragma unroll
    for (int mt = 0; mt < 4; ++mt)
#pragma unroll
        for (int nt = 0; nt < 4; ++nt) {
            int r0 = wm * 64 + mt * 16 + (lane >> 2);
            int c0 = wn * 32 + nt * 8 + ((lane & 3) << 1);
            xbuf[r0 * 136 + c0]           = acc[mt][nt][0];
            xbuf[r0 * 136 + c0 + 1]       = acc[mt][nt][1];
            xbuf[(r0 + 8) * 136 + c0]     = acc[mt][nt][2];
            xbuf[(r0 + 8) * 136 + c0 + 1] = acc[mt][nt][3];
        }
    __syncthreads();

    // LN + relu epilogue: 2 threads per row (128 rows), 8B vector smem reads
    {
        int row = tid >> 1;
        int cb = (tid & 1) * 64;
        float s = 0.f, s2 = 0.f;
#pragma unroll
        for (int c16 = 0; c16 < 16; ++c16) {
            int c = cb + c16 * 4;
            uint32_t o = swz(row + 1, c);
            uint2 H2 = *(uint2*)(smc + SH_HI + o);
            uint2 L2 = *(uint2*)(smc + SH_LO + o);
            __half2 hh0 = *(__half2*)&H2.x, hh1 = *(__half2*)&H2.y;
            __half2 ll0 = *(__half2*)&L2.x, ll1 = *(__half2*)&L2.y;
            float x0 = __low2float(hh0)  + __low2float(ll0)  + xbuf[row * 136 + c]     + b2s[c];
            float x1 = __high2float(hh0) + __high2float(ll0) + xbuf[row * 136 + c + 1] + b2s[c + 1];
            float x2 = __low2float(hh1)  + __low2float(ll1)  + xbuf[row * 136 + c + 2] + b2s[c + 2];
            float x3 = __high2float(hh1) + __high2float(ll1) + xbuf[row * 136 + c + 3] + b2s[c + 3];
            s += x0 + x1 + x2 + x3;
            s2 += x0 * x0 + x1 * x1 + x2 * x2 + x3 * x3;
        }
        s  += __shfl_xor_sync(0xffffffffu, s, 1);
        s2 += __shfl_xor_sync(0xffffffffu, s2, 1);
        float mu = s * (1.f / 128.f);
        float var = fmaxf(s2 * (1.f / 128.f) - mu * mu, 0.f);
        float rs = rsqrtf(var + EPSF);
        float* outp = bsel(outsel) + ((size_t)b * LL + t0 + row) * HH;
#pragma unroll
        for (int c16 = 0; c16 < 16; ++c16) {
            int c = cb + c16 * 4;
            uint32_t o = swz(row + 1, c);
            uint2 H2 = *(uint2*)(smc + SH_HI + o);
            uint2 L2 = *(uint2*)(smc + SH_LO + o);
            __half2 hh0 = *(__half2*)&H2.x, hh1 = *(__half2*)&H2.y;
            __half2 ll0 = *(__half2*)&L2.x, ll1 = *(__half2*)&L2.y;
            float x0 = __low2float(hh0)  + __low2float(ll0)  + xbuf[row * 136 + c]     + b2s[c];
            float x1 = __high2float(hh0) + __high2float(ll0) + xbuf[row * 136 + c + 1] + b2s[c + 1];
            float x2 = __low2float(hh1)  + __low2float(ll1)  + xbuf[row * 136 + c + 2] + b2s[c + 2];
            float x3 = __high2float(hh1) + __high2float(ll1) + xbuf[row * 136 + c + 3] + b2s[c + 3];
            float4 ov;
            ov.x = fmaxf((x0 - mu) * rs * gs[c]     + bes[c],     0.f);
            ov.y = fmaxf((x1 - mu) * rs * gs[c + 1] + bes[c + 1], 0.f);
            ov.z = fmaxf((x2 - mu) * rs * gs[c + 2] + bes[c + 2], 0.f);
            ov.w = fmaxf((x3 - mu) * rs * gs[c + 3] + bes[c + 3], 0.f);
            *(float4*)(outp + c) = ov;
        }
    }
}

// h = 0.5*(fwd + rev) -> out; scores = h @ Ws + bs
__global__ void k_combine(float* __restrict__ out, const float* __restrict__ Ws,
                          const float* __restrict__ bs) {
    int row = blockIdx.x * 8 + (threadIdx.x >> 5);
    int lane = threadIdx.x & 31;
    int c = lane * 4;
    size_t base = (size_t)row * HH + c;
    float4 a = *(const float4*)(g_buf2 + base);
    float4 bq = *(const float4*)(g_buf0 + base);
    float4 h;
    h.x = 0.5f * (a.x + bq.x); h.y = 0.5f * (a.y + bq.y);
    h.z = 0.5f * (a.z + bq.z); h.w = 0.5f * (a.w + bq.w);
    *(float4*)(out + base) = h;
    float4 w = *(const float4*)(Ws + c);
    float s = h.x * w.x + h.y * w.y + h.z * w.z + h.w * w.w;
#pragma unroll
    for (int m = 16; m; m >>= 1) s += __shfl_xor_sync(0xffffffffu, s, m);
    if (lane == 0) g_scores[row] = s + bs[0];
}

__global__ void k_softmax() {
    __shared__ float red[256];
    int b = blockIdx.x, tid = threadIdx.x;
    float* sc = g_scores + (size_t)b * LL;
    float m = -1e30f;
    for (int k = 0; k < 16; ++k) m = fmaxf(m, sc[tid + k * 256]);
    red[tid] = m; __syncthreads();
    for (int st = 128; st; st >>= 1) {
        if (tid < st) red[tid] = fmaxf(red[tid], red[tid + st]);
        __syncthreads();
    }
    m = red[0]; __syncthreads();
    float s = 0.f;
    for (int k = 0; k < 16; ++k) s += __expf(sc[tid + k * 256] - m);
    red[tid] = s; __syncthreads();
    for (int st = 128; st; st >>= 1) {
        if (tid < st) red[tid] += red[tid + st];
        __syncthreads();
    }
    float inv = 1.f / red[0];
    for (int k = 0; k < 16; ++k) {
        int i = tid + k * 256;
        sc[i] = __expf(sc[i] - m) * inv;
    }
}

__global__ void k_pool(const float* __restrict__ h) {
    int j = blockIdx.x, b = blockIdx.y, c = threadIdx.x;
    const float* w = g_scores + (size_t)b * LL + j * 512;
    const float* hp = h + ((size_t)b * LL + j * 512) * HH + c;
    float acc = 0.f;
#pragma unroll 4
    for (int l = 0; l < 512; ++l) acc += w[l] * hp[(size_t)l * HH];
    g_part[(b * 8 + j) * HH + c] = acc;
}

__global__ void k_reduce(float* __restrict__ outp) {
    int b = blockIdx.x, c = threadIdx.x;
    float s = 0.f;
#pragma unroll
    for (int j = 0; j < 8; ++j) s += g_part[(b * 8 + j) * HH + c];
    outp[(size_t)b * HH + c] = s;
}

extern "C" void kernel_launch(void* const* d_in, const int* in_sizes, int n_in,
                              void* d_out, int out_size) {
    const float* tokens = (const float*)d_in[0];
    const float* Wp     = (const float*)d_in[1];
    const float* bp     = (const float*)d_in[2];
    const float* W1     = (const float*)d_in[3];
    const float* b1     = (const float*)d_in[4];
    const float* W2     = (const float*)d_in[5];
    const float* b2     = (const float*)d_in[6];
    const float* gamma  = (const float*)d_in[7];
    const float* beta   = (const float*)d_in[8];
    const float* Ws     = (const float*)d_in[9];
    const float* bs     = (const float*)d_in[10];
    float* out = (float*)d_out;

    cudaFuncSetAttribute(k_layer, cudaFuncAttributeMaxDynamicSharedMemorySize, SMEM_TOTAL);

    k_prep<<<768, 256>>>(W1, W2);
    k_proj<<<32768, 256>>>(tokens, Wp, bp);

    dim3 lgrid(32, 64);
    // forward: buf0 -> 1 -> 2 -> 1 -> 2
    k_layer<<<lgrid, 256, SMEM_TOTAL>>>(0, 1, 0, 1, b1, b2, gamma, beta);
    k_layer<<<lgrid, 256, SMEM_TOTAL>>>(1, 1, 1, 2, b1, b2, gamma, beta);
    k_layer<<<lgrid, 256, SMEM_TOTAL>>>(2, 1, 2, 1, b1, b2, gamma, beta);
    k_layer<<<lgrid, 256, SMEM_TOTAL>>>(3, 1, 1, 2, b1, b2, gamma, beta);
    // reverse: buf0 -> 1 -> 0 -> 1 -> 0
    k_layer<<<lgrid, 256, SMEM_TOTAL>>>(0, -1, 0, 1, b1, b2, gamma, beta);
    k_layer<<<lgrid, 256, SMEM_TOTAL>>>(1, -1, 1, 0, b1, b2, gamma, beta);
    k_layer<<<lgrid, 256, SMEM_TOTAL>>>(2, -1, 0, 1, b1, b2, gamma, beta);
    k_layer<<<lgrid, 256, SMEM_TOTAL>>>(3, -1, 1, 0, b1, b2, gamma, beta);

    k_combine<<<32768, 256>>>(out, Ws, bs);
    k_softmax<<<64, 256>>>();
    k_pool<<<dim3(8, 64), 128>>>(out);
    k_reduce<<<64, 128>>>(out + (size_t)BB * LL * HH);
}

// round 16
// speedup vs baseline: 1.0343x; 1.0165x over previous
#include <cuda_runtime.h>
#include <cuda_fp16.h>
#include <cstdint>
#include <cstddef>

#define BB 64
#define LL 4096
#define HH 128
#define NLAYER 4
#define EPSF 1e-5f

// ---- smem layout (bytes), M=128 tile ----
#define SH_HI   0
#define SH_LO   33280
#define TMP_HI  66560
#define TMP_LO  99328
#define BST     132096         // 4 stages x 8KB (4KB hi + 4KB lo)
#define BIAS    164864
#define SMEM_TOTAL 166912
// xbuf fp32 (128 x 136 = 69632B) aliases TMP_HI..(+4KB into BST), used only after GEMM2

static __device__ __align__(16) float g_buf0[(size_t)BB * LL * HH];
static __device__ __align__(16) float g_buf1[(size_t)BB * LL * HH];
static __device__ __align__(16) float g_buf2[(size_t)BB * LL * HH];
static __device__ __align__(16) float g_buf3[(size_t)BB * LL * HH];
static __device__ __align__(16) float g_buf4[(size_t)BB * LL * HH];
static __device__ __align__(16) __half g_W1hi[NLAYER * 3 * HH * HH];
static __device__ __align__(16) __half g_W1lo[NLAYER * 3 * HH * HH];
static __device__ __align__(16) __half g_W2hi[NLAYER * HH * HH];
static __device__ __align__(16) __half g_W2lo[NLAYER * HH * HH];
static __device__ float g_scores[BB * LL];
static __device__ float g_part[BB * 8 * HH];

__device__ __forceinline__ float* bsel(int i) {
    return i == 0 ? g_buf0 : i == 1 ? g_buf1 : i == 2 ? g_buf2 : i == 3 ? g_buf3 : g_buf4;
}

__device__ __forceinline__ uint32_t swz(int r, int c) {
    return (uint32_t)((r << 8) + (((c >> 3) ^ (r & 7)) << 4) + ((c & 7) << 1));
}
__device__ __forceinline__ void ldsm4(uint32_t a, uint32_t* r) {
    asm volatile("ldmatrix.sync.aligned.m8n8.x4.shared.b16 {%0,%1,%2,%3}, [%4];\n"
                 : "=r"(r[0]), "=r"(r[1]), "=r"(r[2]), "=r"(r[3]) : "r"(a));
}
__device__ __forceinline__ void ldsm4t(uint32_t a, uint32_t* r) {
    asm volatile("ldmatrix.sync.aligned.m8n8.x4.trans.shared.b16 {%0,%1,%2,%3}, [%4];\n"
                 : "=r"(r[0]), "=r"(r[1]), "=r"(r[2]), "=r"(r[3]) : "r"(a));
}
__device__ __forceinline__ void mma_16816(float* d, const uint32_t* a, const uint32_t* b) {
    asm volatile(
        "mma.sync.aligned.m16n8k16.row.col.f32.f16.f16.f32 "
        "{%0,%1,%2,%3}, {%4,%5,%6,%7}, {%8,%9}, {%0,%1,%2,%3};\n"
        : "+f"(d[0]), "+f"(d[1]), "+f"(d[2]), "+f"(d[3])
        : "r"(a[0]), "r"(a[1]), "r"(a[2]), "r"(a[3]), "r"(b[0]), "r"(b[1]));
}

// stage one 16x128 k-tile of hi/lo weights (8KB) with 512 threads: 1 cp.async each
__device__ __forceinline__ void bload(const __half* Bhi, const __half* Blo,
                                      int c, int stage, int tid, uint32_t sb) {
    int t2 = tid & 255;
    int plane = tid >> 8;                 // 0: hi, 1: lo
    int r = t2 >> 4, q = t2 & 15;
    uint32_t dst = sb + BST + (uint32_t)stage * 8192u + (uint32_t)plane * 4096u
                 + (uint32_t)(r * 256 + ((q ^ (r & 7)) << 4));
    const __half* src = (plane ? Blo : Bhi) + (c * 16 + r) * 128 + q * 8;
    asm volatile("cp.async.ca.shared.global [%0], [%1], 16;\n" :: "r"(dst), "l"(src));
}
#define CPCOMMIT() asm volatile("cp.async.commit_group;\n")

__global__ void k_prep(const float* __restrict__ W1, const float* __restrict__ W2) {
    int i = blockIdx.x * blockDim.x + threadIdx.x;
    if (i < NLAYER * 3 * HH * HH) {
        float v = W1[i];
        __half h = __float2half_rn(v);
        g_W1hi[i] = h;
        g_W1lo[i] = __float2half_rn(v - __half2float(h));
    }
    if (i < NLAYER * HH * HH) {
        float v = W2[i];
        __half h = __float2half_rn(v);
        g_W2hi[i] = h;
        g_W2lo[i] = __float2half_rn(v - __half2float(h));
    }
}

__global__ void k_proj(const float* __restrict__ tokens, const float* __restrict__ Wp,
                       const float* __restrict__ bp) {
    int g = blockIdx.x * blockDim.x + threadIdx.x;
    int tok = g >> 5;
    int c = (g & 31) * 4;
    const float* tr = tokens + (size_t)tok * 8;
    float tv[8];
#pragma unroll
    for (int i = 0; i < 8; ++i) tv[i] = tr[i];
    float4 acc;
    acc.x = bp[c]; acc.y = bp[c + 1]; acc.z = bp[c + 2]; acc.w = bp[c + 3];
#pragma unroll
    for (int i = 0; i < 8; ++i) {
        float4 w = *(const float4*)(Wp + i * HH + c);
        acc.x += tv[i] * w.x; acc.y += tv[i] * w.y;
        acc.z += tv[i] * w.z; acc.w += tv[i] * w.w;
    }
    *(float4*)(g_buf0 + (size_t)tok * HH + c) = acc;
}

__global__ void __launch_bounds__(512, 1)
k_layer(int layer, int in_f, int out_f, int in_r, int out_r,
        const float* __restrict__ b1g, const float* __restrict__ b2g,
        const float* __restrict__ gammag, const float* __restrict__ betag) {
    extern __shared__ char smc[];
    const uint32_t sb = (uint32_t)__cvta_generic_to_shared(smc);
    const int tid = threadIdx.x;
    const int lane = tid & 31, warp = tid >> 5;
    const int wm = warp >> 2, wn = warp & 3;   // 4m x 4n; warp tile m32 x n32
    const int lr = lane & 15;
    const int lc = (lane >> 4) << 3;
    const int b = blockIdx.y;
    const int t0 = blockIdx.x * 128;
    const int dirn = blockIdx.z == 0 ? 1 : -1;
    const int insel = blockIdx.z == 0 ? in_f : in_r;
    const int outsel = blockIdx.z == 0 ? out_f : out_r;

    float* b1s = (float*)(smc + BIAS);
    float* b2s = b1s + 128;
    float* gs  = b1s + 256;
    float* bes = b1s + 384;
    if (tid < 128) {
        b1s[tid] = b1g[layer * HH + tid];
        b2s[tid] = b2g[layer * HH + tid];
        gs[tid]  = gammag[layer * HH + tid];
        bes[tid] = betag[layer * HH + tid];
    }

    // load h rows [t0-1, t0+128] (circular) as split fp16, 8B vector stores
    const float* hin = bsel(insel);
    for (int f = tid; f < 130 * 32; f += 512) {
        int r = f >> 5, c4 = f & 31;
        int gl = (t0 - 1 + r + LL) & (LL - 1);
        float4 v = *(const float4*)(hin + ((size_t)b * LL + gl) * HH + c4 * 4);
        __half2 h01 = __floats2half2_rn(v.x, v.y);
        __half2 h23 = __floats2half2_rn(v.z, v.w);
        __half2 l01 = __floats2half2_rn(v.x - __low2float(h01), v.y - __high2float(h01));
        __half2 l23 = __floats2half2_rn(v.z - __low2float(h23), v.w - __high2float(h23));
        uint32_t o = swz(r, c4 * 4);
        uint2 hv, lv;
        hv.x = *(uint32_t*)&h01; hv.y = *(uint32_t*)&h23;
        lv.x = *(uint32_t*)&l01; lv.y = *(uint32_t*)&l23;
        *(uint2*)(smc + SH_HI + o) = hv;
        *(uint2*)(smc + SH_LO + o) = lv;
    }
    __syncthreads();

    float acc[2][4][4];
#pragma unroll
    for (int mt = 0; mt < 2; ++mt)
#pragma unroll
        for (int nt = 0; nt < 4; ++nt)
#pragma unroll
            for (int e = 0; e < 4; ++e) acc[mt][nt][e] = 0.f;

    const __half* W1hi = g_W1hi + (size_t)layer * 3 * HH * HH;
    const __half* W1lo = g_W1lo + (size_t)layer * 3 * HH * HH;
    const __half* W2hi = g_W2hi + (size_t)layer * HH * HH;
    const __half* W2lo = g_W2lo + (size_t)layer * HH * HH;

    // ---- GEMM1: K=384, 24 k-tiles, 4-stage ring depth 3 ----
    bload(W1hi, W1lo, 0, 0, tid, sb); CPCOMMIT();
    bload(W1hi, W1lo, 1, 1, tid, sb); CPCOMMIT();
    bload(W1hi, W1lo, 2, 2, tid, sb); CPCOMMIT();
#pragma unroll
    for (int c = 0; c < 24; ++c) {
        if (c <= 21)      asm volatile("cp.async.wait_group 2;\n");
        else if (c == 22) asm volatile("cp.async.wait_group 1;\n");
        else              asm volatile("cp.async.wait_group 0;\n");
        __syncthreads();
        if (c + 3 < 24) {
            bload(W1hi, W1lo, c + 3, (c + 3) & 3, tid, sb); CPCOMMIT();
        }
        int off = ((c >> 3) - 1) * dirn;
        int arb = wm * 32 + 1 + off + lr;
        int acol = (c & 7) * 16 + lc;
        uint32_t ahi[2][4], alo[2][4], bhi[2][4], blo[2][4];
#pragma unroll
        for (int mt = 0; mt < 2; ++mt) {
            ldsm4(sb + SH_HI + swz(arb + mt * 16, acol), ahi[mt]);
            ldsm4(sb + SH_LO + swz(arb + mt * 16, acol), alo[mt]);
        }
        uint32_t bbs = sb + BST + (uint32_t)(c & 3) * 8192u;
#pragma unroll
        for (int g = 0; g < 2; ++g) {
            uint32_t ba = bbs + swz(lr, wn * 32 + g * 16 + lc);
            ldsm4t(ba, bhi[g]);
            ldsm4t(ba + 4096u, blo[g]);
        }
#pragma unroll
        for (int mt = 0; mt < 2; ++mt)
#pragma unroll
            for (int g = 0; g < 2; ++g)
#pragma unroll
                for (int j = 0; j < 2; ++j) {
                    mma_16816(acc[mt][g * 2 + j], ahi[mt], &bhi[g][j * 2]);
                    mma_16816(acc[mt][g * 2 + j], ahi[mt], &blo[g][j * 2]);
                    mma_16816(acc[mt][g * 2 + j], alo[mt], &bhi[g][j * 2]);
                }
    }

    // bias + relu -> split fp16 -> TMP
#pragma unroll
    for (int mt = 0; mt < 2; ++mt)
#pragma unroll
        for (int nt = 0; nt < 4; ++nt) {
            int r0 = wm * 32 + mt * 16 + (lane >> 2);
            int c0 = wn * 32 + nt * 8 + ((lane & 3) << 1);
            float v0 = fmaxf(acc[mt][nt][0] + b1s[c0],     0.f);
            float v1 = fmaxf(acc[mt][nt][1] + b1s[c0 + 1], 0.f);
            float v2 = fmaxf(acc[mt][nt][2] + b1s[c0],     0.f);
            float v3 = fmaxf(acc[mt][nt][3] + b1s[c0 + 1], 0.f);
            __half2 hA = __floats2half2_rn(v0, v1);
            __half2 hB = __floats2half2_rn(v2, v3);
            __half2 lA = __floats2half2_rn(v0 - __low2float(hA), v1 - __high2float(hA));
            __half2 lB = __floats2half2_rn(v2 - __low2float(hB), v3 - __high2float(hB));
            *(__half2*)(smc + TMP_HI + swz(r0, c0))     = hA;
            *(__half2*)(smc + TMP_LO + swz(r0, c0))     = lA;
            *(__half2*)(smc + TMP_HI + swz(r0 + 8, c0)) = hB;
            *(__half2*)(smc + TMP_LO + swz(r0 + 8, c0)) = lB;
            acc[mt][nt][0] = acc[mt][nt][1] = acc[mt][nt][2] = acc[mt][nt][3] = 0.f;
        }

    // ---- GEMM2: K=128, 8 k-tiles; preload W2 stages 0-2 (slots free: their last
    //      reads were G1 iters 20/21/22, all before the c=23 barrier) ----
    bload(W2hi, W2lo, 0, 0, tid, sb); CPCOMMIT();
    bload(W2hi, W2lo, 1, 1, tid, sb); CPCOMMIT();
    bload(W2hi, W2lo, 2, 2, tid, sb); CPCOMMIT();
#pragma unroll
    for (int c = 0; c < 8; ++c) {
        if (c <= 5)      asm volatile("cp.async.wait_group 2;\n");
        else if (c == 6) asm volatile("cp.async.wait_group 1;\n");
        else             asm volatile("cp.async.wait_group 0;\n");
        __syncthreads();   // c==0: also makes TMP stores visible
        if (c + 3 < 8) {
            bload(W2hi, W2lo, c + 3, (c + 3) & 3, tid, sb); CPCOMMIT();
        }
        int acol = c * 16 + lc;
        int arb = wm * 32 + lr;
        uint32_t ahi[2][4], alo[2][4], bhi[2][4], blo[2][4];
#pragma unroll
        for (int mt = 0; mt < 2; ++mt) {
            ldsm4(sb + TMP_HI + swz(arb + mt * 16, acol), ahi[mt]);
            ldsm4(sb + TMP_LO + swz(arb + mt * 16, acol), alo[mt]);
        }
        uint32_t bbs = sb + BST + (uint32_t)(c & 3) * 8192u;
#pragma unroll
        for (int g = 0; g < 2; ++g) {
            uint32_t ba = bbs + swz(lr, wn * 32 + g * 16 + lc);
            ldsm4t(ba, bhi[g]);
            ldsm4t(ba + 4096u, blo[g]);
        }
#pragma unroll
        for (int mt = 0; mt < 2; ++mt)
#pragma unroll
            for (int g = 0; g < 2; ++g)
#pragma unroll
                for (int j = 0; j < 2; ++j) {
                    mma_16816(acc[mt][g * 2 + j], ahi[mt], &bhi[g][j * 2]);
                    mma_16816(acc[mt][g * 2 + j], ahi[mt], &blo[g][j * 2]);
                    mma_16816(acc[mt][g * 2 + j], alo[mt], &bhi[g][j * 2]);
                }
    }
    __syncthreads();   // all TMP reads done before xbuf aliases it

    // stash delta fp32 in xbuf (aliases TMP + first 4KB of BST slot 0)
    float* xbuf = (float*)(smc + TMP_HI);
#pragma unroll
    for (int mt = 0; mt < 2; ++mt)
#pragma unroll
        for (int nt = 0; nt < 4; ++nt) {
            int r0 = wm * 32 + mt * 16 + (lane >> 2);
            int c0 = wn * 32 + nt * 8 + ((lane & 3) << 1);
            xbuf[r0 * 136 + c0]           = acc[mt][nt][0];
            xbuf[r0 * 136 + c0 + 1]       = acc[mt][nt][1];
            xbuf[(r0 + 8) * 136 + c0]     = acc[mt][nt][2];
            xbuf[(r0 + 8) * 136 + c0 + 1] = acc[mt][nt][3];
        }
    __syncthreads();

    // LN + relu epilogue: 4 threads per row (128 rows), 8B vector smem reads
    {
        int row = tid >> 2;
        int cb = (tid & 3) * 32;
        float s = 0.f, s2 = 0.f;
#pragma unroll
        for (int c8 = 0; c8 < 8; ++c8) {
            int c = cb + c8 * 4;
            uint32_t o = swz(row + 1, c);
            uint2 H2 = *(uint2*)(smc + SH_HI + o);
            uint2 L2 = *(uint2*)(smc + SH_LO + o);
            __half2 hh0 = *(__half2*)&H2.x, hh1 = *(__half2*)&H2.y;
            __half2 ll0 = *(__half2*)&L2.x, ll1 = *(__half2*)&L2.y;
            float x0 = __low2float(hh0)  + __low2float(ll0)  + xbuf[row * 136 + c]     + b2s[c];
            float x1 = __high2float(hh0) + __high2float(ll0) + xbuf[row * 136 + c + 1] + b2s[c + 1];
            float x2 = __low2float(hh1)  + __low2float(ll1)  + xbuf[row * 136 + c + 2] + b2s[c + 2];
            float x3 = __high2float(hh1) + __high2float(ll1) + xbuf[row * 136 + c + 3] + b2s[c + 3];
            s += x0 + x1 + x2 + x3;
            s2 += x0 * x0 + x1 * x1 + x2 * x2 + x3 * x3;
        }
        s  += __shfl_xor_sync(0xffffffffu, s, 1);
        s2 += __shfl_xor_sync(0xffffffffu, s2, 1);
        s  += __shfl_xor_sync(0xffffffffu, s, 2);
        s2 += __shfl_xor_sync(0xffffffffu, s2, 2);
        float mu = s * (1.f / 128.f);
        float var = fmaxf(s2 * (1.f / 128.f) - mu * mu, 0.f);
        float rs = rsqrtf(var + EPSF);
        float* outp = bsel(outsel) + ((size_t)b * LL + t0 + row) * HH;
#pragma unroll
        for (int c8 = 0; c8 < 8; ++c8) {
            int c = cb + c8 * 4;
            uint32_t o = swz(row + 1, c);
            uint2 H2 = *(uint2*)(smc + SH_HI + o);
            uint2 L2 = *(uint2*)(smc + SH_LO + o);
            __half2 hh0 = *(__half2*)&H2.x, hh1 = *(__half2*)&H2.y;
            __half2 ll0 = *(__half2*)&L2.x, ll1 = *(__half2*)&L2.y;
            float x0 = __low2float(hh0)  + __low2float(ll0)  + xbuf[row * 136 + c]     + b2s[c];
            float x1 = __high2float(hh0) + __high2float(ll0) + xbuf[row * 136 + c + 1] + b2s[c + 1];
            float x2 = __low2float(hh1)  + __low2float(ll1)  + xbuf[row * 136 + c + 2] + b2s[c + 2];
            float x3 = __high2float(hh1) + __high2float(ll1) + xbuf[row * 136 + c + 3] + b2s[c + 3];
            float4 ov;
            ov.x = fmaxf((x0 - mu) * rs * gs[c]     + bes[c],     0.f);
            ov.y = fmaxf((x1 - mu) * rs * gs[c + 1] + bes[c + 1], 0.f);
            ov.z = fmaxf((x2 - mu) * rs * gs[c + 2] + bes[c + 2], 0.f);
            ov.w = fmaxf((x3 - mu) * rs * gs[c + 3] + bes[c + 3], 0.f);
            *(float4*)(outp + c) = ov;
        }
    }
}

// h = 0.5*(fwd + rev) -> out; scores = h @ Ws + bs
__global__ void k_combine(float* __restrict__ out, const float* __restrict__ Ws,
                          const float* __restrict__ bs) {
    int row = blockIdx.x * 8 + (threadIdx.x >> 5);
    int lane = threadIdx.x & 31;
    int c = lane * 4;
    size_t base = (size_t)row * HH + c;
    float4 a = *(const float4*)(g_buf2 + base);
    float4 bq = *(const float4*)(g_buf4 + base);
    float4 h;
    h.x = 0.5f * (a.x + bq.x); h.y = 0.5f * (a.y + bq.y);
    h.z = 0.5f * (a.z + bq.z); h.w = 0.5f * (a.w + bq.w);
    *(float4*)(out + base) = h;
    float4 w = *(const float4*)(Ws + c);
    float s = h.x * w.x + h.y * w.y + h.z * w.z + h.w * w.w;
#pragma unroll
    for (int m = 16; m; m >>= 1) s += __shfl_xor_sync(0xffffffffu, s, m);
    if (lane == 0) g_scores[row] = s + bs[0];
}

__global__ void k_softmax() {
    __shared__ float red[256];
    int b = blockIdx.x, tid = threadIdx.x;
    float* sc = g_scores + (size_t)b * LL;
    float m = -1e30f;
    for (int k = 0; k < 16; ++k) m = fmaxf(m, sc[tid + k * 256]);
    red[tid] = m; __syncthreads();
    for (int st = 128; st; st >>= 1) {
        if (tid < st) red[tid] = fmaxf(red[tid], red[tid + st]);
        __syncthreads();
    }
    m = red[0]; __syncthreads();
    float s = 0.f;
    for (int k = 0; k < 16; ++k) s += __expf(sc[tid + k * 256] - m);
    red[tid] = s; __syncthreads();
    for (int st = 128; st; st >>= 1) {
        if (tid < st) red[tid] += red[tid + st];
        __syncthreads();
    }
    float inv = 1.f / red[0];
    for (int k = 0; k < 16; ++k) {
        int i = tid + k * 256;
        sc[i] = __expf(sc[i] - m) * inv;
    }
}

__global__ void k_pool(const float* __restrict__ h) {
    int j = blockIdx.x, b = blockIdx.y, c = threadIdx.x;
    const float* w = g_scores + (size_t)b * LL + j * 512;
    const float* hp = h + ((size_t)b * LL + j * 512) * HH + c;
    float acc = 0.f;
#pragma unroll 4
    for (int l = 0; l < 512; ++l) acc += w[l] * hp[(size_t)l * HH];
    g_part[(b * 8 + j) * HH + c] = acc;
}

__global__ void k_reduce(float* __restrict__ outp) {
    int b = blockIdx.x, c = threadIdx.x;
    float s = 0.f;
#pragma unroll
    for (int j = 0; j < 8; ++j) s += g_part[(b * 8 + j) * HH + c];
    outp[(size_t)b * HH + c] = s;
}

extern "C" void kernel_launch(void* const* d_in, const int* in_sizes, int n_in,
                              void* d_out, int out_size) {
    const float* tokens = (const float*)d_in[0];
    const float* Wp     = (const float*)d_in[1];
    const float* bp     = (const float*)d_in[2];
    const float* W1     = (const float*)d_in[3];
    const float* b1     = (const float*)d_in[4];
    const float* W2     = (const float*)d_in[5];
    const float* b2     = (const float*)d_in[6];
    const float* gamma  = (const float*)d_in[7];
    const float* beta   = (const float*)d_in[8];
    const float* Ws     = (const float*)d_in[9];
    const float* bs     = (const float*)d_in[10];
    float* out = (float*)d_out;

    cudaFuncSetAttribute(k_layer, cudaFuncAttributeMaxDynamicSharedMemorySize, SMEM_TOTAL);

    k_prep<<<768, 256>>>(W1, W2);
    k_proj<<<32768, 256>>>(tokens, Wp, bp);

    // merged fwd+rev per layer: z=0 fwd (buf0->1->2->1->2), z=1 rev (buf0->3->4->3->4)
    dim3 lgrid(32, 64, 2);
    k_layer<<<lgrid, 512, SMEM_TOTAL>>>(0, 0, 1, 0, 3, b1, b2, gamma, beta);
    k_layer<<<lgrid, 512, SMEM_TOTAL>>>(1, 1, 2, 3, 4, b1, b2, gamma, beta);
    k_layer<<<lgrid, 512, SMEM_TOTAL>>>(2, 2, 1, 4, 3, b1, b2, gamma, beta);
    k_layer<<<lgrid, 512, SMEM_TOTAL>>>(3, 1, 2, 3, 4, b1, b2, gamma, beta);

    k_combine<<<32768, 256>>>(out, Ws, bs);
    k_softmax<<<64, 256>>>();
    k_pool<<<dim3(8, 64), 128>>>(out);
    k_reduce<<<64, 128>>>(out + (size_t)BB * LL * HH);
}

// round 17
// speedup vs baseline: 1.1767x; 1.1376x over previous
#include <cuda_runtime.h>
#include <cuda_fp16.h>
#include <cstdint>
#include <cstddef>

#define BB 64
#define LL 4096
#define HH 128
#define NLAYER 4
#define EPSF 1e-5f

// ---- smem layout (bytes), M=64 tile, single-precision activations ----
#define SH      0              // 66 rows x 256B fp16 h tile
#define TMP     16896          // 64 rows x 256B fp16 tmp
#define BST     33280          // 4 stages x 8KB (4KB Whi + 4KB Wlo)
#define BIAS    66048
#define SMEM_TOTAL 68096
// xbuf fp32 (64 x 136 = 34816B) aliases TMP..BST+2.4KB, used only after GEMM2

static __device__ __align__(16) float g_buf0[(size_t)BB * LL * HH];
static __device__ __align__(16) float g_buf1[(size_t)BB * LL * HH];
static __device__ __align__(16) float g_buf2[(size_t)BB * LL * HH];
static __device__ __align__(16) __half g_W1hi[NLAYER * 3 * HH * HH];
static __device__ __align__(16) __half g_W1lo[NLAYER * 3 * HH * HH];
static __device__ __align__(16) __half g_W2hi[NLAYER * HH * HH];
static __device__ __align__(16) __half g_W2lo[NLAYER * HH * HH];
static __device__ float g_scores[BB * LL];
static __device__ float g_part[BB * 8 * HH];

__device__ __forceinline__ float* bsel(int i) {
    return i == 0 ? g_buf0 : i == 1 ? g_buf1 : g_buf2;
}

__device__ __forceinline__ uint32_t swz(int r, int c) {
    return (uint32_t)((r << 8) + (((c >> 3) ^ (r & 7)) << 4) + ((c & 7) << 1));
}
__device__ __forceinline__ void ldsm4(uint32_t a, uint32_t* r) {
    asm volatile("ldmatrix.sync.aligned.m8n8.x4.shared.b16 {%0,%1,%2,%3}, [%4];\n"
                 : "=r"(r[0]), "=r"(r[1]), "=r"(r[2]), "=r"(r[3]) : "r"(a));
}
__device__ __forceinline__ void ldsm4t(uint32_t a, uint32_t* r) {
    asm volatile("ldmatrix.sync.aligned.m8n8.x4.trans.shared.b16 {%0,%1,%2,%3}, [%4];\n"
                 : "=r"(r[0]), "=r"(r[1]), "=r"(r[2]), "=r"(r[3]) : "r"(a));
}
__device__ __forceinline__ void mma_16816(float* d, const uint32_t* a, const uint32_t* b) {
    asm volatile(
        "mma.sync.aligned.m16n8k16.row.col.f32.f16.f16.f32 "
        "{%0,%1,%2,%3}, {%4,%5,%6,%7}, {%8,%9}, {%0,%1,%2,%3};\n"
        : "+f"(d[0]), "+f"(d[1]), "+f"(d[2]), "+f"(d[3])
        : "r"(a[0]), "r"(a[1]), "r"(a[2]), "r"(a[3]), "r"(b[0]), "r"(b[1]));
}

// stage one 16x128 k-tile of hi/lo weights into 4-stage smem ring
__device__ __forceinline__ void bload(const __half* Bhi, const __half* Blo,
                                      int c, int stage, int tid, uint32_t sb) {
    int r = tid >> 4, q = tid & 15;
    uint32_t dst = sb + BST + (uint32_t)stage * 8192u
                 + (uint32_t)(r * 256 + ((q ^ (r & 7)) << 4));
    const __half* s1 = Bhi + (c * 16 + r) * 128 + q * 8;
    const __half* s2 = Blo + (c * 16 + r) * 128 + q * 8;
    asm volatile("cp.async.ca.shared.global [%0], [%1], 16;\n" :: "r"(dst), "l"(s1));
    asm volatile("cp.async.ca.shared.global [%0], [%1], 16;\n" :: "r"(dst + 4096u), "l"(s2));
}
#define CPCOMMIT() asm volatile("cp.async.commit_group;\n")

__global__ void k_prep(const float* __restrict__ W1, const float* __restrict__ W2) {
    int i = blockIdx.x * blockDim.x + threadIdx.x;
    if (i < NLAYER * 3 * HH * HH) {
        float v = W1[i];
        __half h = __float2half_rn(v);
        g_W1hi[i] = h;
        g_W1lo[i] = __float2half_rn(v - __half2float(h));
    }
    if (i < NLAYER * HH * HH) {
        float v = W2[i];
        __half h = __float2half_rn(v);
        g_W2hi[i] = h;
        g_W2lo[i] = __float2half_rn(v - __half2float(h));
    }
}

__global__ void k_proj(const float* __restrict__ tokens, const float* __restrict__ Wp,
                       const float* __restrict__ bp) {
    int g = blockIdx.x * blockDim.x + threadIdx.x;
    int tok = g >> 5;
    int c = (g & 31) * 4;
    const float* tr = tokens + (size_t)tok * 8;
    float tv[8];
#pragma unroll
    for (int i = 0; i < 8; ++i) tv[i] = tr[i];
    float4 acc;
    acc.x = bp[c]; acc.y = bp[c + 1]; acc.z = bp[c + 2]; acc.w = bp[c + 3];
#pragma unroll
    for (int i = 0; i < 8; ++i) {
        float4 w = *(const float4*)(Wp + i * HH + c);
        acc.x += tv[i] * w.x; acc.y += tv[i] * w.y;
        acc.z += tv[i] * w.z; acc.w += tv[i] * w.w;
    }
    *(float4*)(g_buf0 + (size_t)tok * HH + c) = acc;
}

__global__ void __launch_bounds__(256, 2)
k_layer(int layer, int dirn, int insel, int outsel,
        const float* __restrict__ b1g, const float* __restrict__ b2g,
        const float* __restrict__ gammag, const float* __restrict__ betag) {
    extern __shared__ char smc[];
    const uint32_t sb = (uint32_t)__cvta_generic_to_shared(smc);
    const int tid = threadIdx.x;
    const int lane = tid & 31, warp = tid >> 5;
    const int wm = warp & 1, wn = warp >> 1;   // 2m x 4n; warp tile m32 x n32
    const int lr = lane & 15;
    const int lc = (lane >> 4) << 3;
    const int b = blockIdx.y;
    const int t0 = blockIdx.x * 64;

    float* b1s = (float*)(smc + BIAS);
    float* b2s = b1s + 128;
    float* gs  = b1s + 256;
    float* bes = b1s + 384;
    if (tid < 128) {
        b1s[tid] = b1g[layer * HH + tid];
        b2s[tid] = b2g[layer * HH + tid];
        gs[tid]  = gammag[layer * HH + tid];
        bes[tid] = betag[layer * HH + tid];
    }

    // load h rows [t0-1, t0+64] (circular) as single fp16, 8B vector stores
    const float* hin = bsel(insel);
    for (int f = tid; f < 66 * 32; f += 256) {
        int r = f >> 5, c4 = f & 31;
        int gl = (t0 - 1 + r + LL) & (LL - 1);
        float4 v = *(const float4*)(hin + ((size_t)b * LL + gl) * HH + c4 * 4);
        __half2 h01 = __floats2half2_rn(v.x, v.y);
        __half2 h23 = __floats2half2_rn(v.z, v.w);
        uint2 hv;
        hv.x = *(uint32_t*)&h01; hv.y = *(uint32_t*)&h23;
        *(uint2*)(smc + SH + swz(r, c4 * 4)) = hv;
    }
    __syncthreads();

    float acc[2][4][4];
#pragma unroll
    for (int mt = 0; mt < 2; ++mt)
#pragma unroll
        for (int nt = 0; nt < 4; ++nt)
#pragma unroll
            for (int e = 0; e < 4; ++e) acc[mt][nt][e] = 0.f;

    const __half* W1hi = g_W1hi + (size_t)layer * 3 * HH * HH;
    const __half* W1lo = g_W1lo + (size_t)layer * 3 * HH * HH;
    const __half* W2hi = g_W2hi + (size_t)layer * HH * HH;
    const __half* W2lo = g_W2lo + (size_t)layer * HH * HH;

    // ---- GEMM1: K=384, 24 k-tiles, 4-stage ring depth 3 ----
    bload(W1hi, W1lo, 0, 0, tid, sb); CPCOMMIT();
    bload(W1hi, W1lo, 1, 1, tid, sb); CPCOMMIT();
    bload(W1hi, W1lo, 2, 2, tid, sb); CPCOMMIT();
#pragma unroll
    for (int c = 0; c < 24; ++c) {
        if (c <= 21)      asm volatile("cp.async.wait_group 2;\n");
        else if (c == 22) asm volatile("cp.async.wait_group 1;\n");
        else              asm volatile("cp.async.wait_group 0;\n");
        __syncthreads();
        if (c + 3 < 24) {
            bload(W1hi, W1lo, c + 3, (c + 3) & 3, tid, sb); CPCOMMIT();
        }
        int off = ((c >> 3) - 1) * dirn;
        int arb = wm * 32 + 1 + off + lr;
        int acol = (c & 7) * 16 + lc;
        uint32_t ah[2][4], bhi[2][4], blo[2][4];
#pragma unroll
        for (int mt = 0; mt < 2; ++mt)
            ldsm4(sb + SH + swz(arb + mt * 16, acol), ah[mt]);
        uint32_t bbs = sb + BST + (uint32_t)(c & 3) * 8192u;
#pragma unroll
        for (int g = 0; g < 2; ++g) {
            uint32_t ba = bbs + swz(lr, wn * 32 + g * 16 + lc);
            ldsm4t(ba, bhi[g]);
            ldsm4t(ba + 4096u, blo[g]);
        }
#pragma unroll
        for (int mt = 0; mt < 2; ++mt)
#pragma unroll
            for (int g = 0; g < 2; ++g)
#pragma unroll
                for (int j = 0; j < 2; ++j) {
                    mma_16816(acc[mt][g * 2 + j], ah[mt], &bhi[g][j * 2]);
                    mma_16816(acc[mt][g * 2 + j], ah[mt], &blo[g][j * 2]);
                }
    }

    // bias + relu -> fp16 -> TMP (single plane)
#pragma unroll
    for (int mt = 0; mt < 2; ++mt)
#pragma unroll
        for (int nt = 0; nt < 4; ++nt) {
            int r0 = wm * 32 + mt * 16 + (lane >> 2);
            int c0 = wn * 32 + nt * 8 + ((lane & 3) << 1);
            float v0 = fmaxf(acc[mt][nt][0] + b1s[c0],     0.f);
            float v1 = fmaxf(acc[mt][nt][1] + b1s[c0 + 1], 0.f);
            float v2 = fmaxf(acc[mt][nt][2] + b1s[c0],     0.f);
            float v3 = fmaxf(acc[mt][nt][3] + b1s[c0 + 1], 0.f);
            *(__half2*)(smc + TMP + swz(r0, c0))     = __floats2half2_rn(v0, v1);
            *(__half2*)(smc + TMP + swz(r0 + 8, c0)) = __floats2half2_rn(v2, v3);
            acc[mt][nt][0] = acc[mt][nt][1] = acc[mt][nt][2] = acc[mt][nt][3] = 0.f;
        }

    // ---- GEMM2: K=128, 8 k-tiles; preload W2 stages 0-2 (slots free: last reads
    //      were G1 iters 20/21/22, all before the c=23 barrier) ----
    bload(W2hi, W2lo, 0, 0, tid, sb); CPCOMMIT();
    bload(W2hi, W2lo, 1, 1, tid, sb); CPCOMMIT();
    bload(W2hi, W2lo, 2, 2, tid, sb); CPCOMMIT();
#pragma unroll
    for (int c = 0; c < 8; ++c) {
        if (c <= 5)      asm volatile("cp.async.wait_group 2;\n");
        else if (c == 6) asm volatile("cp.async.wait_group 1;\n");
        else             asm volatile("cp.async.wait_group 0;\n");
        __syncthreads();   // c==0: also makes TMP stores visible
        if (c + 3 < 8) {
            bload(W2hi, W2lo, c + 3, (c + 3) & 3, tid, sb); CPCOMMIT();
        }
        int acol = c * 16 + lc;
        int arb = wm * 32 + lr;
        uint32_t ah[2][4], bhi[2][4], blo[2][4];
#pragma unroll
        for (int mt = 0; mt < 2; ++mt)
            ldsm4(sb + TMP + swz(arb + mt * 16, acol), ah[mt]);
        uint32_t bbs = sb + BST + (uint32_t)(c & 3) * 8192u;
#pragma unroll
        for (int g = 0; g < 2; ++g) {
            uint32_t ba = bbs + swz(lr, wn * 32 + g * 16 + lc);
            ldsm4t(ba, bhi[g]);
            ldsm4t(ba + 4096u, blo[g]);
        }
#pragma unroll
        for (int mt = 0; mt < 2; ++mt)
#pragma unroll
            for (int g = 0; g < 2; ++g)
#pragma unroll
                for (int j = 0; j < 2; ++j) {
                    mma_16816(acc[mt][g * 2 + j], ah[mt], &bhi[g][j * 2]);
                    mma_16816(acc[mt][g * 2 + j], ah[mt], &blo[g][j * 2]);
                }
    }
    __syncthreads();   // all TMP reads done before xbuf aliases it

    // stash delta fp32 in xbuf (aliases TMP + BST slots 0-2; staging done)
    float* xbuf = (float*)(smc + TMP);
#pragma unroll
    for (int mt = 0; mt < 2; ++mt)
#pragma unroll
        for (int nt = 0; nt < 4; ++nt) {
            int r0 = wm * 32 + mt * 16 + (lane >> 2);
            int c0 = wn * 32 + nt * 8 + ((lane & 3) << 1);
            xbuf[r0 * 136 + c0]           = acc[mt][nt][0];
            xbuf[r0 * 136 + c0 + 1]       = acc[mt][nt][1];
            xbuf[(r0 + 8) * 136 + c0]     = acc[mt][nt][2];
            xbuf[(r0 + 8) * 136 + c0 + 1] = acc[mt][nt][3];
        }
    __syncthreads();

    // LN + relu epilogue: 4 threads per row; residual h re-read from gmem (L2-hot, exact fp32)
    {
        int row = tid >> 2;
        int cb = (tid & 3) * 32;
        const float* hrow = hin + ((size_t)b * LL + t0 + row) * HH;
        float s = 0.f, s2 = 0.f;
#pragma unroll
        for (int c8 = 0; c8 < 8; ++c8) {
            int c = cb + c8 * 4;
            float4 hv = *(const float4*)(hrow + c);
            float x0 = hv.x + xbuf[row * 136 + c]     + b2s[c];
            float x1 = hv.y + xbuf[row * 136 + c + 1] + b2s[c + 1];
            float x2 = hv.z + xbuf[row * 136 + c + 2] + b2s[c + 2];
            float x3 = hv.w + xbuf[row * 136 + c + 3] + b2s[c + 3];
            s += x0 + x1 + x2 + x3;
            s2 += x0 * x0 + x1 * x1 + x2 * x2 + x3 * x3;
        }
        s  += __shfl_xor_sync(0xffffffffu, s, 1);
        s2 += __shfl_xor_sync(0xffffffffu, s2, 1);
        s  += __shfl_xor_sync(0xffffffffu, s, 2);
        s2 += __shfl_xor_sync(0xffffffffu, s2, 2);
        float mu = s * (1.f / 128.f);
        float var = fmaxf(s2 * (1.f / 128.f) - mu * mu, 0.f);
        float rs = rsqrtf(var + EPSF);
        float* outp = bsel(outsel) + ((size_t)b * LL + t0 + row) * HH;
#pragma unroll
        for (int c8 = 0; c8 < 8; ++c8) {
            int c = cb + c8 * 4;
            float4 hv = *(const float4*)(hrow + c);
            float x0 = hv.x + xbuf[row * 136 + c]     + b2s[c];
            float x1 = hv.y + xbuf[row * 136 + c + 1] + b2s[c + 1];
            float x2 = hv.z + xbuf[row * 136 + c + 2] + b2s[c + 2];
            float x3 = hv.w + xbuf[row * 136 + c + 3] + b2s[c + 3];
            float4 ov;
            ov.x = fmaxf((x0 - mu) * rs * gs[c]     + bes[c],     0.f);
            ov.y = fmaxf((x1 - mu) * rs * gs[c + 1] + bes[c + 1], 0.f);
            ov.z = fmaxf((x2 - mu) * rs * gs[c + 2] + bes[c + 2], 0.f);
            ov.w = fmaxf((x3 - mu) * rs * gs[c + 3] + bes[c + 3], 0.f);
            *(float4*)(outp + c) = ov;
        }
    }
}

// h = 0.5*(fwd + rev) -> out; scores = h @ Ws + bs
__global__ void k_combine(float* __restrict__ out, const float* __restrict__ Ws,
                          const float* __restrict__ bs) {
    int row = blockIdx.x * 8 + (threadIdx.x >> 5);
    int lane = threadIdx.x & 31;
    int c = lane * 4;
    size_t base = (size_t)row * HH + c;
    float4 a = *(const float4*)(g_buf2 + base);
    float4 bq = *(const float4*)(g_buf0 + base);
    float4 h;
    h.x = 0.5f * (a.x + bq.x); h.y = 0.5f * (a.y + bq.y);
    h.z = 0.5f * (a.z + bq.z); h.w = 0.5f * (a.w + bq.w);
    *(float4*)(out + base) = h;
    float4 w = *(const float4*)(Ws + c);
    float s = h.x * w.x + h.y * w.y + h.z * w.z + h.w * w.w;
#pragma unroll
    for (int m = 16; m; m >>= 1) s += __shfl_xor_sync(0xffffffffu, s, m);
    if (lane == 0) g_scores[row] = s + bs[0];
}

__global__ void k_softmax() {
    __shared__ float red[256];
    int b = blockIdx.x, tid = threadIdx.x;
    float* sc = g_scores + (size_t)b * LL;
    float m = -1e30f;
    for (int k = 0; k < 16; ++k) m = fmaxf(m, sc[tid + k * 256]);
    red[tid] = m; __syncthreads();
    for (int st = 128; st; st >>= 1) {
        if (tid < st) red[tid] = fmaxf(red[tid], red[tid + st]);
        __syncthreads();
    }
    m = red[0]; __syncthreads();
    float s = 0.f;
    for (int k = 0; k < 16; ++k) s += __expf(sc[tid + k * 256] - m);
    red[tid] = s; __syncthreads();
    for (int st = 128; st; st >>= 1) {
        if (tid < st) red[tid] += red[tid + st];
        __syncthreads();
    }
    float inv = 1.f / red[0];
    for (int k = 0; k < 16; ++k) {
        int i = tid + k * 256;
        sc[i] = __expf(sc[i] - m) * inv;
    }
}

__global__ void k_pool(const float* __restrict__ h) {
    int j = blockIdx.x, b = blockIdx.y, c = threadIdx.x;
    const float* w = g_scores + (size_t)b * LL + j * 512;
    const float* hp = h + ((size_t)b * LL + j * 512) * HH + c;
    float acc = 0.f;
#pragma unroll 4
    for (int l = 0; l < 512; ++l) acc += w[l] * hp[(size_t)l * HH];
    g_part[(b * 8 + j) * HH + c] = acc;
}

__global__ void k_reduce(float* __restrict__ outp) {
    int b = blockIdx.x, c = threadIdx.x;
    float s = 0.f;
#pragma unroll
    for (int j = 0; j < 8; ++j) s += g_part[(b * 8 + j) * HH + c];
    outp[(size_t)b * HH + c] = s;
}

extern "C" void kernel_launch(void* const* d_in, const int* in_sizes, int n_in,
                              void* d_out, int out_size) {
    const float* tokens = (const float*)d_in[0];
    const float* Wp     = (const float*)d_in[1];
    const float* bp     = (const float*)d_in[2];
    const float* W1     = (const float*)d_in[3];
    const float* b1     = (const float*)d_in[4];
    const float* W2     = (const float*)d_in[5];
    const float* b2     = (const float*)d_in[6];
    const float* gamma  = (const float*)d_in[7];
    const float* beta   = (const float*)d_in[8];
    const float* Ws     = (const float*)d_in[9];
    const float* bs     = (const float*)d_in[10];
    float* out = (float*)d_out;

    cudaFuncSetAttribute(k_layer, cudaFuncAttributeMaxDynamicSharedMemorySize, SMEM_TOTAL);

    k_prep<<<768, 256>>>(W1, W2);
    k_proj<<<32768, 256>>>(tokens, Wp, bp);

    dim3 lgrid(64, 64);
    // forward: buf0 -> 1 -> 2 -> 1 -> 2
    k_layer<<<lgrid, 256, SMEM_TOTAL>>>(0, 1, 0, 1, b1, b2, gamma, beta);
    k_layer<<<lgrid, 256, SMEM_TOTAL>>>(1, 1, 1, 2, b1, b2, gamma, beta);
    k_layer<<<lgrid, 256, SMEM_TOTAL>>>(2, 1, 2, 1, b1, b2, gamma, beta);
    k_layer<<<lgrid, 256, SMEM_TOTAL>>>(3, 1, 1, 2, b1, b2, gamma, beta);
    // reverse: buf0 -> 1 -> 0 -> 1 -> 0
    k_layer<<<lgrid, 256, SMEM_TOTAL>>>(0, -1, 0, 1, b1, b2, gamma, beta);
    k_layer<<<lgrid, 256, SMEM_TOTAL>>>(1, -1, 1, 0, b1, b2, gamma, beta);
    k_layer<<<lgrid, 256, SMEM_TOTAL>>>(2, -1, 0, 1, b1, b2, gamma, beta);
    k_layer<<<lgrid, 256, SMEM_TOTAL>>>(3, -1, 1, 0, b1, b2, gamma, beta);

    k_combine<<<32768, 256>>>(out, Ws, bs);
    k_softmax<<<64, 256>>>();
    k_pool<<<dim3(8, 64), 128>>>(out);
    k_reduce<<<64, 128>>>(out + (size_t)BB * LL * HH);
}